// round 11
// baseline (speedup 1.0000x reference)
#include <cuda_runtime.h>
#include <cuda_bf16.h>
#include <cstdint>

#define D_EMBED 512
#define N_CLUST 64
#define ROWS_CTA 128
#define X_STAGES 3
#define X_STAGE_BYTES 8192                       // 8 warps x 16 rows x 64B
#define SC2_OFF (X_STAGES * X_STAGE_BYTES)       // 24576
#define SMEM_BYTES (SC2_OFF + N_CLUST * 4 + 8 * 4)

// ---------------- device scratch (no allocations allowed) ----------------
__device__ float    g_c2[N_CLUST];
__device__ double   g_acc = 0.0;
__device__ unsigned g_ctr = 0;
// B fragments, vectorized: [kstep(32)][npair(4)][lane(32)] -> uint4 = {nt=2np (b0,b1), nt=2np+1 (b0,b1)}
__device__ __align__(16) uint4 g_bfragv[32 * 4 * 32];

// ---------------- helpers ----------------
__device__ __forceinline__ unsigned pack_bf16(float lo, float hi) {
    unsigned r;
    asm("cvt.rn.bf16x2.f32 %0, %1, %2;" : "=r"(r) : "f"(hi), "f"(lo));
    return r;
}

__device__ __forceinline__ void mma16816(float* c,
                                         unsigned a0, unsigned a1, unsigned a2, unsigned a3,
                                         unsigned b0, unsigned b1) {
    asm volatile(
        "mma.sync.aligned.m16n8k16.row.col.f32.bf16.bf16.f32 "
        "{%0,%1,%2,%3}, {%4,%5,%6,%7}, {%8,%9}, {%0,%1,%2,%3};"
        : "+f"(c[0]), "+f"(c[1]), "+f"(c[2]), "+f"(c[3])
        : "r"(a0), "r"(a1), "r"(a2), "r"(a3), "r"(b0), "r"(b1));
}

__device__ __forceinline__ void cp16(unsigned dst, const float* src) {
    asm volatile("cp.async.cg.shared.global [%0], [%1], 16;" :: "r"(dst), "l"(src));
}
#define CP_COMMIT() asm volatile("cp.async.commit_group;" ::: "memory")
#define CP_WAIT2()  asm volatile("cp.async.wait_group 2;" ::: "memory")

__device__ __forceinline__ float4 lds128(unsigned addr) {
    float4 v;
    asm volatile("ld.shared.v4.f32 {%0,%1,%2,%3}, [%4];"
                 : "=f"(v.x), "=f"(v.y), "=f"(v.z), "=f"(v.w) : "r"(addr));
    return v;
}

// alpha may arrive as int32 / int64 / float32 (python scalar 100). Decode robustly.
__device__ __forceinline__ float decode_alpha(const void* p) {
    int iv = *reinterpret_cast<const int*>(p);
    unsigned u = (unsigned)iv;
    unsigned ex = (u >> 23) & 0xffu;
    if (ex >= 110u && ex <= 150u) return __int_as_float(iv);
    if (iv == 0) {
        double dv = *reinterpret_cast<const double*>(p);
        if (dv > 1e-6 && dv < 1e9) return (float)dv;
    }
    return (float)iv;
}

// ---------------- kernel 1: fused setup (c2 + vectorized bf16 B-fragments) ----------------
// k-permutation as before: logical k-pairs of the m16n8k16 B fragment map to
// physical columns (tig*4+{0,1})/(tig*4+{2,3}) so the A side consumes one float4.
__global__ void setup_kernel(const float* __restrict__ cent) {
    int id = blockIdx.x * blockDim.x + threadIdx.x;   // 0..4095
    {
        int lane = id & 31, np = (id >> 5) & 3, ks = id >> 7;
        int kb = ks * 16 + (lane & 3) * 4;
        int n0 = (2 * np) * 8 + (lane >> 2);
        int n1 = (2 * np + 1) * 8 + (lane >> 2);
        float4 v0 = *reinterpret_cast<const float4*>(cent + n0 * D_EMBED + kb);
        float4 v1 = *reinterpret_cast<const float4*>(cent + n1 * D_EMBED + kb);
        uint4 r;
        r.x = pack_bf16(v0.x, v0.y);
        r.y = pack_bf16(v0.z, v0.w);
        r.z = pack_bf16(v1.x, v1.y);
        r.w = pack_bf16(v1.z, v1.w);
        g_bfragv[id] = r;
    }
    if (id < N_CLUST * 32) {
        int w = id >> 5, lane = id & 31;
        const float* c = cent + w * D_EMBED;
        float s = 0.f;
        #pragma unroll
        for (int i = 0; i < D_EMBED / 32; i++) {
            float v = c[i * 32 + lane];
            s = fmaf(v, v, s);
        }
        #pragma unroll
        for (int m = 16; m; m >>= 1) s += __shfl_xor_sync(0xffffffffu, s, m);
        if (lane == 0) g_c2[w] = s;
    }
}

// ---------------- kernel 2: main fused GEMM + softmax + finalize ----------------
__global__ __launch_bounds__(256, 3)
void main_kernel(const float* __restrict__ x, const void* __restrict__ alphap,
                 float* __restrict__ out, int Ntot) {
    extern __shared__ unsigned char smem_raw[];
    float* sc2 = reinterpret_cast<float*>(smem_raw + SC2_OFF);
    float* swp = sc2 + N_CLUST;

    int tid = threadIdx.x;
    if (tid < N_CLUST) sc2[tid] = g_c2[tid];
    __syncthreads();

    int warp = tid >> 5, lane = tid & 31;
    int g = lane >> 2, tig = lane & 3;
    size_t base = (size_t)blockIdx.x * ROWS_CTA + (size_t)warp * 16;
    // lane's gmem streams: rows base+g and base+g+8, cols tig*4 + ks*16
    const float* xr = x + (base + g) * D_EMBED + tig * 4;

    // per-warp private smem slot: [stage][warp] 1KB; within: (h*8+g)*64 + tig*16
    unsigned sx_lane;
    {
        unsigned sbase;
        asm("{ .reg .u64 t; cvta.to.shared.u64 t, %1; cvt.u32.u64 %0, t; }"
            : "=r"(sbase) : "l"(smem_raw));
        sx_lane = sbase + warp * 1024 + g * 64 + tig * 16;
    }

    float acc[8][4];
    #pragma unroll
    for (int n = 0; n < 8; n++)
        #pragma unroll
        for (int j = 0; j < 4; j++) acc[n][j] = 0.f;

    float xs0 = 0.f, xs1 = 0.f;   // x^2 partials for rows g, g+8

    const uint4* bl = g_bfragv + lane;

    // ---- prologue: stage ks=0 and ks=1 ----
    #pragma unroll
    for (int p = 0; p < 2; p++) {
        unsigned d = sx_lane + p * X_STAGE_BYTES;
        const float* s = xr + p * 16;
        cp16(d,       s);                 // row base+g
        cp16(d + 512, s + 8 * D_EMBED);   // row base+g+8
        CP_COMMIT();
    }

    for (int ks = 0; ks < 32; ks++) {
        if (ks < 30) {
            unsigned d = sx_lane + ((ks + 2) % X_STAGES) * X_STAGE_BYTES;
            const float* s = xr + (ks + 2) * 16;
            cp16(d,       s);
            cp16(d + 512, s + 8 * D_EMBED);
        }
        CP_COMMIT();       // empty group in tail keeps wait numbering exact
        CP_WAIT2();        // group ks complete

        unsigned sxs = sx_lane + (ks % X_STAGES) * X_STAGE_BYTES;
        float4 c0 = lds128(sxs);
        float4 c1 = lds128(sxs + 512);

        xs0 = fmaf(c0.x, c0.x, fmaf(c0.y, c0.y, fmaf(c0.z, c0.z, fmaf(c0.w, c0.w, xs0))));
        xs1 = fmaf(c1.x, c1.x, fmaf(c1.y, c1.y, fmaf(c1.z, c1.z, fmaf(c1.w, c1.w, xs1))));

        unsigned a0 = pack_bf16(c0.x, c0.y), a2 = pack_bf16(c0.z, c0.w);
        unsigned a1 = pack_bf16(c1.x, c1.y), a3 = pack_bf16(c1.z, c1.w);

        const uint4* bk = bl + ks * 128;
        #pragma unroll
        for (int np = 0; np < 4; np++) {
            uint4 b = __ldg(bk + np * 32);
            mma16816(acc[2 * np],     a0, a1, a2, a3, b.x, b.y);
            mma16816(acc[2 * np + 1], a0, a1, a2, a3, b.z, b.w);
        }
    }

    // complete x^2 across the 4-lane tig group (same rows)
    xs0 += __shfl_xor_sync(0xffffffffu, xs0, 1);
    xs0 += __shfl_xor_sync(0xffffffffu, xs0, 2);
    xs1 += __shfl_xor_sync(0xffffffffu, xs1, 1);
    xs1 += __shfl_xor_sync(0xffffffffu, xs1, 2);

    float alpha = decode_alpha(alphap);

    // softmax shift-invariance in x^2: sum(dist*soft) = x2 + sum(t*soft), t = c2 - 2*cross
    float rowsum = 0.f;
    #pragma unroll
    for (int h = 0; h < 2; h++) {
        float dd[16];
        float tmin = 3.4e38f;
        #pragma unroll
        for (int nt = 0; nt < 8; nt++) {
            int n = nt * 8 + tig * 2;
            float t0 = sc2[n]     - 2.f * acc[nt][h * 2 + 0];
            float t1 = sc2[n + 1] - 2.f * acc[nt][h * 2 + 1];
            dd[nt * 2]     = t0;
            dd[nt * 2 + 1] = t1;
            tmin = fminf(tmin, fminf(t0, t1));
        }
        tmin = fminf(tmin, __shfl_xor_sync(0xffffffffu, tmin, 1));
        tmin = fminf(tmin, __shfl_xor_sync(0xffffffffu, tmin, 2));
        float se = 0.f, sw = 0.f;
        #pragma unroll
        for (int i = 0; i < 16; i++) {
            float e = __expf(alpha * (tmin - dd[i]));
            se += e;
            sw = fmaf(dd[i], e, sw);
        }
        se += __shfl_xor_sync(0xffffffffu, se, 1);
        se += __shfl_xor_sync(0xffffffffu, se, 2);
        sw += __shfl_xor_sync(0xffffffffu, sw, 1);
        sw += __shfl_xor_sync(0xffffffffu, sw, 2);
        rowsum += (h == 0 ? xs0 : xs1) + sw / se;   // identical in all 4 tig lanes
    }
    // warp total (each row value duplicated 4x across tig lanes -> scale 0.25)
    #pragma unroll
    for (int m = 16; m; m >>= 1) rowsum += __shfl_xor_sync(0xffffffffu, rowsum, m);
    if (lane == 0) swp[warp] = rowsum * 0.25f;
    __syncthreads();
    if (tid == 0) {
        float s = 0.f;
        #pragma unroll
        for (int i = 0; i < 8; i++) s += swp[i];
        atomicAdd(&g_acc, (double)s);
        __threadfence();
        unsigned t = atomicAdd(&g_ctr, 1u);
        if (t == gridDim.x - 1) {       // last CTA: finalize + reset for graph replay
            out[0] = (float)(0.1 * g_acc / (double)Ntot);
            g_acc = 0.0;
            g_ctr = 0;
            __threadfence();
        }
    }
}

// ---------------- launch ----------------
extern "C" void kernel_launch(void* const* d_in, const int* in_sizes, int n_in,
                              void* d_out, int out_size) {
    const float* x    = (const float*)d_in[0];
    const float* cent = (const float*)d_in[1];
    const void*  ap   = d_in[2];
    int N = in_sizes[0] / D_EMBED;

    cudaFuncSetAttribute(main_kernel, cudaFuncAttributeMaxDynamicSharedMemorySize, SMEM_BYTES);

    setup_kernel<<<16, 256>>>(cent);
    main_kernel<<<N / ROWS_CTA, 256, SMEM_BYTES>>>(x, ap, (float*)d_out, N);
}

// round 12
// speedup vs baseline: 1.5147x; 1.5147x over previous
#include <cuda_runtime.h>
#include <cuda_bf16.h>
#include <cstdint>

#define D_EMBED 512
#define N_CLUST 64
#define ROWS_CTA 512
#define NWARP 16
#define X_STAGES 5
#define X_STAGE_BYTES 32768                      // 16 warps x 2KB
#define SB_OFF (X_STAGES * X_STAGE_BYTES)        // 163840
#define SC2_OFF (SB_OFF + 65536)                 // 229376
#define SMEM_BYTES (SC2_OFF + N_CLUST * 4 + NWARP * 4)   // 229696

// ---------------- device scratch (no allocations allowed) ----------------
__device__ double   g_acc = 0.0;
__device__ unsigned g_ctr = 0;

// ---------------- helpers ----------------
__device__ __forceinline__ unsigned pack_bf16(float lo, float hi) {
    unsigned r;
    asm("cvt.rn.bf16x2.f32 %0, %1, %2;" : "=r"(r) : "f"(hi), "f"(lo));
    return r;
}

__device__ __forceinline__ void mma16816(float* c,
                                         unsigned a0, unsigned a1, unsigned a2, unsigned a3,
                                         unsigned b0, unsigned b1) {
    asm volatile(
        "mma.sync.aligned.m16n8k16.row.col.f32.bf16.bf16.f32 "
        "{%0,%1,%2,%3}, {%4,%5,%6,%7}, {%8,%9}, {%0,%1,%2,%3};"
        : "+f"(c[0]), "+f"(c[1]), "+f"(c[2]), "+f"(c[3])
        : "r"(a0), "r"(a1), "r"(a2), "r"(a3), "r"(b0), "r"(b1));
}

__device__ __forceinline__ void cp16(unsigned dst, const float* src) {
    asm volatile("cp.async.cg.shared.global [%0], [%1], 16;" :: "r"(dst), "l"(src));
}
#define CP_COMMIT() asm volatile("cp.async.commit_group;" ::: "memory")
#define CP_WAIT4()  asm volatile("cp.async.wait_group 4;" ::: "memory")

// alpha may arrive as int32 / int64 / float32 (python scalar 100). Decode robustly.
__device__ __forceinline__ float decode_alpha(const void* p) {
    int iv = *reinterpret_cast<const int*>(p);
    unsigned u = (unsigned)iv;
    unsigned ex = (u >> 23) & 0xffu;
    if (ex >= 110u && ex <= 150u) return __int_as_float(iv);
    if (iv == 0) {
        double dv = *reinterpret_cast<const double*>(p);
        if (dv > 1e-6 && dv < 1e9) return (float)dv;
    }
    return (float)iv;
}

// ---------------- single fused kernel ----------------
__global__ __launch_bounds__(512, 1)
void main_kernel(const float* __restrict__ x, const float* __restrict__ cent,
                 const void* __restrict__ alphap, float* __restrict__ out, int Ntot) {
    extern __shared__ unsigned char smem_raw[];
    uint2* sB  = reinterpret_cast<uint2*>(smem_raw + SB_OFF);
    float* sc2 = reinterpret_cast<float*>(smem_raw + SC2_OFF);
    float* swp = sc2 + N_CLUST;

    int tid = threadIdx.x;
    int warp = tid >> 5, lane = tid & 31;
    int g = lane >> 2, tig = lane & 3;
    size_t base = (size_t)blockIdx.x * ROWS_CTA + (size_t)warp * 32;
    // lane's gmem streams: rows base+g (+8/+16/+24), cols tig*4 + ks*16
    const float* xr = x + (base + g) * D_EMBED + tig * 4;

    // per-warp private x slot: [stage][warp][j][lane] 16B each
    unsigned sx_lane;
    {
        unsigned sbase;
        asm("{ .reg .u64 t; cvta.to.shared.u64 t, %1; cvt.u32.u64 %0, t; }"
            : "=r"(sbase) : "l"(smem_raw));
        sx_lane = sbase + warp * 2048 + lane * 16;
    }

    // ---- prologue FIRST: start the x DRAM stream (stages 0..3) ----
    #pragma unroll
    for (int p = 0; p < 4; p++) {
        unsigned d = sx_lane + p * X_STAGE_BYTES;
        const float* s = xr + p * 16;
        cp16(d,        s);                 // rows base+g
        cp16(d + 512,  s + 8  * D_EMBED);  // rows base+g+8
        cp16(d + 1024, s + 16 * D_EMBED);  // rows base+g+16
        cp16(d + 1536, s + 24 * D_EMBED);  // rows base+g+24
        CP_COMMIT();
    }

    // ---- inline B-fragment build (k-permutation layout) + c2, overlapped ----
    // id = ks*256 + nt*32 + lane; n = nt*8 + lane/4; kb = ks*16 + (lane%4)*4
    #pragma unroll
    for (int i = 0; i < 16; i++) {
        int id = tid + i * 512;
        int bl2 = id & 31, nt = (id >> 5) & 7, ks = id >> 8;
        int n  = nt * 8 + (bl2 >> 2);
        int kb = ks * 16 + (bl2 & 3) * 4;
        float4 v = *reinterpret_cast<const float4*>(cent + n * D_EMBED + kb);
        uint2 r;
        r.x = pack_bf16(v.x, v.y);
        r.y = pack_bf16(v.z, v.w);
        sB[id] = r;
    }
    {   // c2: warp w -> rows 4w..4w+3
        #pragma unroll
        for (int j = 0; j < 4; j++) {
            int r = warp * 4 + j;
            const float* c = cent + r * D_EMBED;
            float s = 0.f;
            #pragma unroll
            for (int i = 0; i < D_EMBED / 32; i++) {
                float v = c[i * 32 + lane];
                s = fmaf(v, v, s);
            }
            #pragma unroll
            for (int m = 16; m; m >>= 1) s += __shfl_xor_sync(0xffffffffu, s, m);
            if (lane == 0) sc2[r] = s;
        }
    }
    __syncthreads();

    float acc[2][8][4];
    #pragma unroll
    for (int m = 0; m < 2; m++)
        #pragma unroll
        for (int n = 0; n < 8; n++)
            #pragma unroll
            for (int j = 0; j < 4; j++) acc[m][n][j] = 0.f;

    float xs[4] = {0.f, 0.f, 0.f, 0.f};  // x^2 partials: [m*2+h]
    const uint2* bl = sB + lane;

    for (int ks = 0; ks < 32; ks++) {
        // issue loads for ks+4 (empty commit in tail keeps wait numbering exact)
        if (ks < 28) {
            unsigned d = sx_lane + ((ks + 4) % X_STAGES) * X_STAGE_BYTES;
            const float* s = xr + (ks + 4) * 16;
            cp16(d,        s);
            cp16(d + 512,  s + 8  * D_EMBED);
            cp16(d + 1024, s + 16 * D_EMBED);
            cp16(d + 1536, s + 24 * D_EMBED);
        }
        CP_COMMIT();
        CP_WAIT4();  // group for ks is complete (<=4 pending: ks+1..ks+4)

        unsigned sxs = sx_lane + (ks % X_STAGES) * X_STAGE_BYTES;
        float4 c00, c01, c10, c11;
        asm volatile("ld.shared.v4.f32 {%0,%1,%2,%3}, [%4];"
                     : "=f"(c00.x), "=f"(c00.y), "=f"(c00.z), "=f"(c00.w) : "r"(sxs));
        asm volatile("ld.shared.v4.f32 {%0,%1,%2,%3}, [%4];"
                     : "=f"(c01.x), "=f"(c01.y), "=f"(c01.z), "=f"(c01.w) : "r"(sxs + 512));
        asm volatile("ld.shared.v4.f32 {%0,%1,%2,%3}, [%4];"
                     : "=f"(c10.x), "=f"(c10.y), "=f"(c10.z), "=f"(c10.w) : "r"(sxs + 1024));
        asm volatile("ld.shared.v4.f32 {%0,%1,%2,%3}, [%4];"
                     : "=f"(c11.x), "=f"(c11.y), "=f"(c11.z), "=f"(c11.w) : "r"(sxs + 1536));

        xs[0] = fmaf(c00.x, c00.x, fmaf(c00.y, c00.y, fmaf(c00.z, c00.z, fmaf(c00.w, c00.w, xs[0]))));
        xs[1] = fmaf(c01.x, c01.x, fmaf(c01.y, c01.y, fmaf(c01.z, c01.z, fmaf(c01.w, c01.w, xs[1]))));
        xs[2] = fmaf(c10.x, c10.x, fmaf(c10.y, c10.y, fmaf(c10.z, c10.z, fmaf(c10.w, c10.w, xs[2]))));
        xs[3] = fmaf(c11.x, c11.x, fmaf(c11.y, c11.y, fmaf(c11.z, c11.z, fmaf(c11.w, c11.w, xs[3]))));

        unsigned a0m0 = pack_bf16(c00.x, c00.y), a2m0 = pack_bf16(c00.z, c00.w);
        unsigned a1m0 = pack_bf16(c01.x, c01.y), a3m0 = pack_bf16(c01.z, c01.w);
        unsigned a0m1 = pack_bf16(c10.x, c10.y), a2m1 = pack_bf16(c10.z, c10.w);
        unsigned a1m1 = pack_bf16(c11.x, c11.y), a3m1 = pack_bf16(c11.z, c11.w);

        const uint2* bk = bl + ks * 256;
        #pragma unroll
        for (int nt = 0; nt < 8; nt++) {
            uint2 b = bk[nt * 32];
            mma16816(acc[0][nt], a0m0, a1m0, a2m0, a3m0, b.x, b.y);
            mma16816(acc[1][nt], a0m1, a1m1, a2m1, a3m1, b.x, b.y);
        }
    }

    // complete x^2 across the 4-lane tig group (same rows)
    #pragma unroll
    for (int i = 0; i < 4; i++) {
        xs[i] += __shfl_xor_sync(0xffffffffu, xs[i], 1);
        xs[i] += __shfl_xor_sync(0xffffffffu, xs[i], 2);
    }

    float alpha = decode_alpha(alphap);

    // softmax shift-invariance in x^2: sum(dist*soft) = x2 + sum(t*soft), t = c2 - 2*cross
    float rowsum = 0.f;
    #pragma unroll
    for (int m = 0; m < 2; m++) {
        #pragma unroll
        for (int h = 0; h < 2; h++) {
            float dd[16];
            float tmin = 3.4e38f;
            #pragma unroll
            for (int nt = 0; nt < 8; nt++) {
                int n = nt * 8 + tig * 2;
                float t0 = sc2[n]     - 2.f * acc[m][nt][h * 2 + 0];
                float t1 = sc2[n + 1] - 2.f * acc[m][nt][h * 2 + 1];
                dd[nt * 2]     = t0;
                dd[nt * 2 + 1] = t1;
                tmin = fminf(tmin, fminf(t0, t1));
            }
            tmin = fminf(tmin, __shfl_xor_sync(0xffffffffu, tmin, 1));
            tmin = fminf(tmin, __shfl_xor_sync(0xffffffffu, tmin, 2));
            float se = 0.f, sw = 0.f;
            #pragma unroll
            for (int i = 0; i < 16; i++) {
                float e = __expf(alpha * (tmin - dd[i]));
                se += e;
                sw = fmaf(dd[i], e, sw);
            }
            se += __shfl_xor_sync(0xffffffffu, se, 1);
            se += __shfl_xor_sync(0xffffffffu, se, 2);
            sw += __shfl_xor_sync(0xffffffffu, sw, 1);
            sw += __shfl_xor_sync(0xffffffffu, sw, 2);
            rowsum += xs[m * 2 + h] + sw / se;  // identical in all 4 tig lanes
        }
    }
    // warp total (each row value duplicated 4x across tig lanes -> scale 0.25)
    #pragma unroll
    for (int m = 16; m; m >>= 1) rowsum += __shfl_xor_sync(0xffffffffu, rowsum, m);
    if (lane == 0) swp[warp] = rowsum * 0.25f;
    __syncthreads();
    if (tid == 0) {
        float s = 0.f;
        #pragma unroll
        for (int i = 0; i < NWARP; i++) s += swp[i];
        atomicAdd(&g_acc, (double)s);
        __threadfence();
        unsigned t = atomicAdd(&g_ctr, 1u);
        if (t == gridDim.x - 1) {       // last CTA: finalize + reset for graph replay
            out[0] = (float)(0.1 * g_acc / (double)Ntot);
            g_acc = 0.0;
            g_ctr = 0;
            __threadfence();
        }
    }
}

// ---------------- launch ----------------
extern "C" void kernel_launch(void* const* d_in, const int* in_sizes, int n_in,
                              void* d_out, int out_size) {
    const float* x    = (const float*)d_in[0];
    const float* cent = (const float*)d_in[1];
    const void*  ap   = d_in[2];
    int N = in_sizes[0] / D_EMBED;

    cudaFuncSetAttribute(main_kernel, cudaFuncAttributeMaxDynamicSharedMemorySize, SMEM_BYTES);

    main_kernel<<<N / ROWS_CTA, 512, SMEM_BYTES>>>(x, cent, ap, (float*)d_out, N);
}